// round 4
// baseline (speedup 1.0000x reference)
#include <cuda_runtime.h>
#include <cuda_fp16.h>
#include <cstdint>

#define BATCH 8192
#define SEQ   40
#define HID   256
#define VOCAB 128

// ===========================================================================
// Global scratch (no cudaMalloc allowed)
// ===========================================================================
__device__ __half g_hh[2][BATCH * HID];   // h hi plane, ping-pong
__device__ __half g_hl[2][BATCH * HID];   // h lo plane
__device__ float  g_c[BATCH * HID];       // cell state
// Wh split + transposed: [jt(8)][split(2)][kc(8)][n(128)][k(32)] fp16 linear.
// n = gate*32 + jj, k = kc*32 + kk.
__device__ __half g_Bp[8][2][8][128 * 32];

__device__ __forceinline__ uint32_t smem_to_u32(const void* p) {
    uint32_t a;
    asm("{ .reg .u64 tmp; cvta.to.shared.u64 tmp, %1; cvt.u32.u64 %0, tmp; }"
        : "=r"(a) : "l"(p));
    return a;
}

#define LDSM_X4(r0, r1, r2, r3, addr) \
    asm volatile("ldmatrix.sync.aligned.m8n8.x4.shared.b16 {%0,%1,%2,%3}, [%4];" \
        : "=r"(r0), "=r"(r1), "=r"(r2), "=r"(r3) : "r"(addr))

#define MMA16816(d, a, b) \
    asm volatile("mma.sync.aligned.m16n8k16.row.col.f32.f16.f16.f32 " \
        "{%0,%1,%2,%3}, {%4,%5,%6,%7}, {%8,%9}, {%0,%1,%2,%3};" \
        : "+f"((d)[0]), "+f"((d)[1]), "+f"((d)[2]), "+f"((d)[3]) \
        : "r"((a)[0]), "r"((a)[1]), "r"((a)[2]), "r"((a)[3]), \
          "r"((b)[0]), "r"((b)[1]))

#define CP_ASYNC16(dst, src) \
    asm volatile("cp.async.cg.shared.global [%0], [%1], 16;" \
        :: "r"(dst), "l"(src) : "memory")
#define CP_COMMIT() asm volatile("cp.async.commit_group;" ::: "memory")
#define CP_WAIT1()  asm volatile("cp.async.wait_group 1;" ::: "memory")
#define CP_WAIT0()  asm volatile("cp.async.wait_group 0;" ::: "memory")

__device__ __forceinline__ float sigf(float x) {
    return 1.0f / (1.0f + __expf(-x));
}
__device__ __forceinline__ float tanh_(float x) {
    float ax = fabsf(x);
    float e  = __expf(-2.0f * ax);
    float r  = (1.0f - e) / (1.0f + e);
    return copysignf(r, x);
}

// ===========================================================================
// Prep: split Wh into fp16 hi/lo, transpose into per-(jt,kc) B tiles
// ===========================================================================
__global__ void prep_wh_kernel(const float* __restrict__ Wh) {
    int e = blockIdx.x * blockDim.x + threadIdx.x;  // 0 .. 262143
    int k = e >> 10, col = e & 1023;
    float v = Wh[e];
    __half hi = __float2half(v);
    __half lo = __float2half(v - __half2float(hi));
    int gate = col >> 8, j = col & 255;
    int jt = j >> 5, jj = j & 31;
    int n = gate * 32 + jj;
    int kc = k >> 5, kk = k & 31;
    g_Bp[jt][0][kc][n * 32 + kk] = hi;
    g_Bp[jt][1][kc][n * 32 + kk] = lo;
}

__global__ void init_state_kernel() {
    int i = blockIdx.x * blockDim.x + threadIdx.x;
    if (i < BATCH * HID) {
        g_hh[0][i] = __float2half(0.0f);
        g_hl[0][i] = __float2half(0.0f);
        g_c[i]     = 0.0f;
    }
}

// ===========================================================================
// LSTM step. CTA: 128 batch x (4 gates x 32 j). 256 threads = 8 warps,
// warp grid 2(M) x 4(jw); warp tile M=64 x (4 gates x 8 j).
// K=256 in 8 chunks of 32, 2-stage cp.async pipeline.
// SMEM stage (40960B): A_hi[10240] A_lo[10240] B_hi[10240] B_lo[10240],
// rows padded to 80B (conflict-free ldmatrix without swizzle).
// ===========================================================================
#define ROWB       80
#define PLANE_SZ   (128 * ROWB)      // 10240
#define STAGE_SZ   (4 * PLANE_SZ)    // 40960
#define SMEM_TOTAL (2 * STAGE_SZ)    // 81920

__global__ __launch_bounds__(256, 2) void lstm_step_kernel(
    int t,
    const int*   __restrict__ inputs,   // [BATCH, SEQ]
    const float* __restrict__ Wx,       // [128, 1024]
    const float* __restrict__ bias)     // [1024]
{
    extern __shared__ __align__(128) unsigned char smem[];
    const uint32_t sbase = smem_to_u32(smem);
    const int tid  = threadIdx.x;
    const int lane = tid & 31, wid = tid >> 5;
    const int mw = wid >> 2;          // 0..1  (64-row M slab)
    const int jw = wid & 3;           // 0..3  (8-col j slab)
    const int b0 = blockIdx.x * 128;
    const int jt = blockIdx.y;        // 0..7
    const int j0 = jt * 32;

    const __half* __restrict__ hh_in = g_hh[t & 1];
    const __half* __restrict__ hl_in = g_hl[t & 1];
    __half* __restrict__ hh_out = g_hh[(t + 1) & 1];
    __half* __restrict__ hl_out = g_hl[(t + 1) & 1];

    // per-thread copy geometry (2 tasks of (A16B + B16B) per i-iter, 4 iters)
    const int cp_s = tid >> 7;                 // plane (tid 0-127 -> hi, 128-255 -> lo)
    const int cp_r = (tid >> 1) & 63;          // base row (x2 rows per thread pair set)
    // simpler: task = tid + i*256 decomposed inside loop

    float acc[4][4][4];
#pragma unroll
    for (int mt = 0; mt < 4; mt++)
#pragma unroll
        for (int g = 0; g < 4; g++)
#pragma unroll
            for (int e = 0; e < 4; e++) acc[mt][g][e] = 0.0f;

    // ldmatrix per-lane geometry
    const int p  = lane >> 3;        // quadrant 0..3
    const int l7 = lane & 7;
    const int rA_base = mw * 64 + (p & 1) * 8 + l7;   // + mt*16
    const int cA_base = (p >> 1);                      // + ks*2
    const int gB = p >> 1;
    const int cB_base = (p & 1);                       // + ks*2
    const int nB_base = jw * 8 + l7;                   // + gate*32

    // ---- issue one chunk's cp.async (A hi/lo + B hi/lo) into stage stg
#define ISSUE_CHUNK(kc, stg) do { \
    const uint32_t sb_ = sbase + (stg) * STAGE_SZ; \
    _Pragma("unroll") \
    for (int i_ = 0; i_ < 4; i_++) { \
        int task_ = tid + i_ * 256; \
        int s_ = task_ >> 9, r_ = (task_ >> 2) & 127, c_ = task_ & 3; \
        const __half* ha_ = s_ ? hl_in : hh_in; \
        const char* asrc_ = (const char*)(ha_ + (size_t)(b0 + r_) * HID + (kc) * 32) + c_ * 16; \
        CP_ASYNC16(sb_ + s_ * PLANE_SZ + r_ * ROWB + c_ * 16, asrc_); \
        const char* bsrc_ = (const char*)(&g_Bp[jt][s_][kc][0]) + r_ * 64 + c_ * 16; \
        CP_ASYNC16(sb_ + 2 * PLANE_SZ + s_ * PLANE_SZ + r_ * ROWB + c_ * 16, bsrc_); \
    } \
    CP_COMMIT(); \
} while (0)

    ISSUE_CHUNK(0, 0);
    ISSUE_CHUNK(1, 1);

#pragma unroll 1
    for (int kc = 0; kc < 8; kc++) {
        if (kc == 7) { CP_WAIT0(); } else { CP_WAIT1(); }
        __syncthreads();

        const uint32_t sb = sbase + (kc & 1) * STAGE_SZ;
#pragma unroll
        for (int ks = 0; ks < 2; ks++) {
            uint32_t ah[4][4], al[4][4], bh[4][2], bl[4][2];
            const int cA = cA_base + ks * 2;
            const int cBv = cB_base + ks * 2;
#pragma unroll
            for (int mt = 0; mt < 4; mt++) {
                int row = rA_base + mt * 16;
                uint32_t off = row * ROWB + cA * 16;
                LDSM_X4(ah[mt][0], ah[mt][1], ah[mt][2], ah[mt][3], sb + off);
                LDSM_X4(al[mt][0], al[mt][1], al[mt][2], al[mt][3],
                        sb + PLANE_SZ + off);
            }
#pragma unroll
            for (int gp = 0; gp < 2; gp++) {
                int rowB = (gp * 2 + gB) * 32 + nB_base;
                uint32_t off = rowB * ROWB + cBv * 16;
                LDSM_X4(bh[gp * 2][0], bh[gp * 2][1],
                        bh[gp * 2 + 1][0], bh[gp * 2 + 1][1],
                        sb + 2 * PLANE_SZ + off);
                LDSM_X4(bl[gp * 2][0], bl[gp * 2][1],
                        bl[gp * 2 + 1][0], bl[gp * 2 + 1][1],
                        sb + 3 * PLANE_SZ + off);
            }
#pragma unroll
            for (int mt = 0; mt < 4; mt++)
#pragma unroll
                for (int g = 0; g < 4; g++) {
                    MMA16816(acc[mt][g], ah[mt], bh[g]);
                    MMA16816(acc[mt][g], ah[mt], bl[g]);
                    MMA16816(acc[mt][g], al[mt], bh[g]);
                }
        }
        __syncthreads();   // all warps done reading stage (kc&1)
        if (kc + 2 < 8) ISSUE_CHUNK(kc + 2, kc & 1);
    }

    // ---- Epilogue: z = acc + Wx[char] + bias -> gates -> c, h(hi/lo)
    const int gq = lane >> 2, t4 = lane & 3;
    const int jcol = j0 + jw * 8 + t4 * 2;     // absolute hidden j (even)

    float2 bias2[4];
#pragma unroll
    for (int g = 0; g < 4; g++)
        bias2[g] = *(const float2*)&bias[g * 256 + jcol];

#pragma unroll
    for (int mt = 0; mt < 4; mt++) {
#pragma unroll
        for (int rr = 0; rr < 2; rr++) {
            const int b  = b0 + mw * 64 + mt * 16 + gq + rr * 8;
            const int ch = inputs[b * SEQ + t];
            const float* wrow = Wx + (size_t)ch * 1024;
            float2 wx2[4];
#pragma unroll
            for (int g = 0; g < 4; g++)
                wx2[g] = *(const float2*)&wrow[g * 256 + jcol];
            float2 c2 = *(const float2*)&g_c[(size_t)b * HID + jcol];

            float cn[2], hn[2];
#pragma unroll
            for (int e = 0; e < 2; e++) {
                float zi = acc[mt][0][rr * 2 + e] + (e ? wx2[0].y : wx2[0].x)
                         + (e ? bias2[0].y : bias2[0].x);
                float zf = acc[mt][1][rr * 2 + e] + (e ? wx2[1].y : wx2[1].x)
                         + (e ? bias2[1].y : bias2[1].x);
                float zg = acc[mt][2][rr * 2 + e] + (e ? wx2[2].y : wx2[2].x)
                         + (e ? bias2[2].y : bias2[2].x);
                float zo = acc[mt][3][rr * 2 + e] + (e ? wx2[3].y : wx2[3].x)
                         + (e ? bias2[3].y : bias2[3].x);
                float ig = sigf(zi), fg = sigf(zf);
                float gg = tanh_(zg), og = sigf(zo);
                float cold = e ? c2.y : c2.x;
                float cc = fg * cold + ig * gg;
                cn[e] = cc;
                hn[e] = og * tanh_(cc);
            }
            *(float2*)&g_c[(size_t)b * HID + jcol] = make_float2(cn[0], cn[1]);

            __half h0 = __float2half(hn[0]), h1 = __float2half(hn[1]);
            __half l0 = __float2half(hn[0] - __half2float(h0));
            __half l1 = __float2half(hn[1] - __half2float(h1));
            *(__half2*)&hh_out[(size_t)b * HID + jcol] = __halves2half2(h0, h1);
            *(__half2*)&hl_out[(size_t)b * HID + jcol] = __halves2half2(l0, l1);
        }
    }
    (void)cp_s; (void)cp_r;
}

// ===========================================================================
// Dense + softmax (h = hh + hl reconstructed in f32)
// ===========================================================================
#define DROWS 8

__global__ __launch_bounds__(128) void dense_softmax_kernel(
    const float* __restrict__ Wd,   // [256, 128]
    const float* __restrict__ bd,   // [128]
    float*       __restrict__ out)  // [BATCH, 128]
{
    const __half* __restrict__ hh = g_hh[SEQ & 1];  // SEQ=40 even -> buffer 0
    const __half* __restrict__ hl = g_hl[SEQ & 1];
    const int b0  = blockIdx.x * DROWS;
    const int tid = threadIdx.x;

    __shared__ float hs[DROWS][HID];
    __shared__ float ls[DROWS][VOCAB];

#pragma unroll
    for (int s = 0; s < DROWS * HID / 128; s++) {
        int e = tid + s * 128;
        size_t ge = (size_t)b0 * HID + e;
        hs[e >> 8][e & 255] = __half2float(hh[ge]) + __half2float(hl[ge]);
    }
    __syncthreads();

    float acc[DROWS];
    float bv = bd[tid];
#pragma unroll
    for (int r = 0; r < DROWS; r++) acc[r] = bv;

#pragma unroll 8
    for (int k = 0; k < HID; k++) {
        float w = Wd[k * VOCAB + tid];
#pragma unroll
        for (int r = 0; r < DROWS; r++) acc[r] += hs[r][k] * w;
    }

#pragma unroll
    for (int r = 0; r < DROWS; r++) ls[r][tid] = acc[r];
    __syncthreads();

    const int w = tid >> 5, lane = tid & 31;
#pragma unroll
    for (int rr = 0; rr < 2; rr++) {
        int r = w * 2 + rr;
        float v[4];
        float m = -1e30f;
#pragma unroll
        for (int q = 0; q < 4; q++) {
            v[q] = ls[r][lane + q * 32];
            m = fmaxf(m, v[q]);
        }
#pragma unroll
        for (int o = 16; o > 0; o >>= 1) m = fmaxf(m, __shfl_xor_sync(0xffffffffu, m, o));
        float s = 0.0f;
#pragma unroll
        for (int q = 0; q < 4; q++) {
            v[q] = __expf(v[q] - m);
            s += v[q];
        }
#pragma unroll
        for (int o = 16; o > 0; o >>= 1) s += __shfl_xor_sync(0xffffffffu, s, o);
        float inv = 1.0f / s;
#pragma unroll
        for (int q = 0; q < 4; q++)
            out[(b0 + r) * VOCAB + lane + q * 32] = v[q] * inv;
    }
}

// ===========================================================================
extern "C" void kernel_launch(void* const* d_in, const int* in_sizes, int n_in,
                              void* d_out, int out_size) {
    const int*   inputs = (const int*)d_in[0];
    const float* Wx     = (const float*)d_in[1];
    const float* Wh     = (const float*)d_in[2];
    const float* b      = (const float*)d_in[3];
    const float* Wd     = (const float*)d_in[4];
    const float* bd     = (const float*)d_in[5];
    float*       out    = (float*)d_out;

    cudaFuncSetAttribute(lstm_step_kernel,
                         cudaFuncAttributeMaxDynamicSharedMemorySize, SMEM_TOTAL);

    init_state_kernel<<<(BATCH * HID + 255) / 256, 256>>>();
    prep_wh_kernel<<<(256 * 1024) / 256, 256>>>(Wh);

    dim3 grid(BATCH / 128, 8);  // 64 x 8 = 512 CTAs
    for (int t = 0; t < SEQ; t++)
        lstm_step_kernel<<<grid, 256, SMEM_TOTAL>>>(t, inputs, Wx, b);

    dense_softmax_kernel<<<BATCH / DROWS, 128>>>(Wd, bd, out);
}

// round 5
// speedup vs baseline: 1.0440x; 1.0440x over previous
#include <cuda_runtime.h>
#include <cuda_fp16.h>
#include <cstdint>

#define BATCH 8192
#define SEQ   40
#define HID   256
#define VOCAB 128

// ===========================================================================
// Global scratch (no cudaMalloc allowed)
// ===========================================================================
__device__ __half g_hh[2][BATCH * HID];   // h hi plane, ping-pong
__device__ __half g_hl[2][BATCH * HID];   // h lo plane
__device__ float  g_c[BATCH * HID];       // cell state
__device__ float  g_Wxb[128 * 1024];      // Wx + bias (bias folded)
// Wh split + transposed: [jt(8)][split(2)][kc(8)][n(128)][k(32)] fp16 linear.
// n = gate*32 + jj, k = kc*32 + kk.
__device__ __half g_Bp[8][2][8][128 * 32];

__device__ __forceinline__ uint32_t smem_to_u32(const void* p) {
    uint32_t a;
    asm("{ .reg .u64 tmp; cvta.to.shared.u64 tmp, %1; cvt.u32.u64 %0, tmp; }"
        : "=r"(a) : "l"(p));
    return a;
}

#define LDSM_X4(r0, r1, r2, r3, addr) \
    asm volatile("ldmatrix.sync.aligned.m8n8.x4.shared.b16 {%0,%1,%2,%3}, [%4];" \
        : "=r"(r0), "=r"(r1), "=r"(r2), "=r"(r3) : "r"(addr))

#define MMA16816(d, a, b) \
    asm volatile("mma.sync.aligned.m16n8k16.row.col.f32.f16.f16.f32 " \
        "{%0,%1,%2,%3}, {%4,%5,%6,%7}, {%8,%9}, {%0,%1,%2,%3};" \
        : "+f"((d)[0]), "+f"((d)[1]), "+f"((d)[2]), "+f"((d)[3]) \
        : "r"((a)[0]), "r"((a)[1]), "r"((a)[2]), "r"((a)[3]), \
          "r"((b)[0]), "r"((b)[1]))

__device__ __forceinline__ float sigf(float x) {
    return 1.0f / (1.0f + __expf(-x));
}
__device__ __forceinline__ float tanh_(float x) {
    float ax = fabsf(x);
    float e  = __expf(-2.0f * ax);
    float r  = (1.0f - e) / (1.0f + e);
    return copysignf(r, x);
}

// ===========================================================================
// Prep kernels
// ===========================================================================
__global__ void prep_wh_kernel(const float* __restrict__ Wh) {
    int e = blockIdx.x * blockDim.x + threadIdx.x;  // 0 .. 262143
    int k = e >> 10, col = e & 1023;
    float v = Wh[e];
    __half hi = __float2half(v);
    __half lo = __float2half(v - __half2float(hi));
    int gate = col >> 8, j = col & 255;
    int jt = j >> 5, jj = j & 31;
    int n = gate * 32 + jj;
    int kc = k >> 5, kk = k & 31;
    g_Bp[jt][0][kc][n * 32 + kk] = hi;
    g_Bp[jt][1][kc][n * 32 + kk] = lo;
}

__global__ void prep_wxb_kernel(const float* __restrict__ Wx,
                                const float* __restrict__ bias) {
    int e = blockIdx.x * blockDim.x + threadIdx.x;  // 0 .. 131071
    g_Wxb[e] = Wx[e] + bias[e & 1023];
}

__global__ void init_state_kernel() {
    int i = blockIdx.x * blockDim.x + threadIdx.x;
    if (i < BATCH * HID) {
        g_hh[0][i] = __float2half(0.0f);
        g_hl[0][i] = __float2half(0.0f);
        g_c[i]     = 0.0f;
    }
}

// ===========================================================================
// LSTM step. CTA: 64 batch x (4 gates x 32 j). 256 threads = 8 warps,
// warp grid 2(mw) x 4(jw); warp tile M=32 x (4 gates x 8 j).
// K=256 in 8 chunks of 32, single SMEM stage, sync copies, 3 CTAs/SM.
// Stage: A_hi[64x80] A_lo[64x80] B_hi[128x80] B_lo[128x80] = 30720 B.
// ===========================================================================
#define ROWB      80
#define A_PLANE   (64 * ROWB)     // 5120
#define B_PLANE   (128 * ROWB)    // 10240
#define OFF_AH    0
#define OFF_AL    A_PLANE
#define OFF_BH    (2 * A_PLANE)
#define OFF_BL    (2 * A_PLANE + B_PLANE)
#define SMEM_TOTAL (2 * A_PLANE + 2 * B_PLANE)   // 30720

__global__ __launch_bounds__(256, 3) void lstm_step_kernel(
    int t,
    const int* __restrict__ inputs)     // [BATCH, SEQ]
{
    extern __shared__ __align__(128) unsigned char smem[];
    const uint32_t sbase = smem_to_u32(smem);
    const int tid  = threadIdx.x;
    const int lane = tid & 31, wid = tid >> 5;
    const int mw = wid >> 2;          // 0..1  (32-row M slab)
    const int jw = wid & 3;           // 0..3  (8-col j slab)
    const int b0 = blockIdx.x * 64;
    const int jt = blockIdx.y;        // 0..7
    const int j0 = jt * 32;

    const __half* __restrict__ hh_in = g_hh[t & 1];
    const __half* __restrict__ hl_in = g_hl[t & 1];
    __half* __restrict__ hh_out = g_hh[(t + 1) & 1];
    __half* __restrict__ hl_out = g_hl[(t + 1) & 1];

    float acc[2][4][4];
#pragma unroll
    for (int mt = 0; mt < 2; mt++)
#pragma unroll
        for (int g = 0; g < 4; g++)
#pragma unroll
            for (int e = 0; e < 4; e++) acc[mt][g][e] = 0.0f;

    // ldmatrix per-lane geometry
    const int p  = lane >> 3;        // quadrant 0..3
    const int l7 = lane & 7;
    const int rA_base = mw * 32 + (p & 1) * 8 + l7;   // + mt*16
    const int cA_base = (p >> 1);                      // 16B unit; + ks*2
    const int gB = p >> 1;
    const int cB_base = (p & 1);                       // + ks*2
    const int nB_base = jw * 8 + l7;                   // + gate*32

    // copy geometry: 6 uniform iterations of 16B units
    const int ar = tid >> 2, ac = tid & 3;       // A: i<2 (256 units/plane)
    const int br = tid >> 1, bc = tid & 1;       // unused alt
    (void)br; (void)bc;

#pragma unroll 1
    for (int kc = 0; kc < 8; kc++) {
        __syncthreads();   // prior chunk fully consumed
        // ---- A planes: i=0 (hi), i=1 (lo): 256 units each; r=tid>>2,c=tid&3
        {
            const __half* src = hh_in + (size_t)(b0 + ar) * HID + kc * 32 + ac * 8;
            *(uint4*)(smem + OFF_AH + ar * ROWB + ac * 16) = *(const uint4*)src;
            const __half* srl = hl_in + (size_t)(b0 + ar) * HID + kc * 32 + ac * 8;
            *(uint4*)(smem + OFF_AL + ar * ROWB + ac * 16) = *(const uint4*)srl;
        }
        // ---- B planes: 512 units each: i covers rows 0-63 / 64-127
#pragma unroll
        for (int i = 0; i < 2; i++) {
            int r = (tid >> 2) + i * 64, c = tid & 3;
            const __half* sh = &g_Bp[jt][0][kc][r * 32 + c * 8];
            const __half* sl = &g_Bp[jt][1][kc][r * 32 + c * 8];
            *(uint4*)(smem + OFF_BH + r * ROWB + c * 16) = *(const uint4*)sh;
            *(uint4*)(smem + OFF_BL + r * ROWB + c * 16) = *(const uint4*)sl;
        }
        __syncthreads();

#pragma unroll
        for (int ks = 0; ks < 2; ks++) {
            uint32_t ah[2][4], al[2][4], bh[4][2], bl[4][2];
            const uint32_t cA = (cA_base + ks * 2) * 16;
            const uint32_t cB = (cB_base + ks * 2) * 16;
#pragma unroll
            for (int mt = 0; mt < 2; mt++) {
                uint32_t off = (rA_base + mt * 16) * ROWB + cA;
                LDSM_X4(ah[mt][0], ah[mt][1], ah[mt][2], ah[mt][3],
                        sbase + OFF_AH + off);
                LDSM_X4(al[mt][0], al[mt][1], al[mt][2], al[mt][3],
                        sbase + OFF_AL + off);
            }
#pragma unroll
            for (int gp = 0; gp < 2; gp++) {
                uint32_t off = ((gp * 2 + gB) * 32 + nB_base) * ROWB + cB;
                LDSM_X4(bh[gp * 2][0], bh[gp * 2][1],
                        bh[gp * 2 + 1][0], bh[gp * 2 + 1][1],
                        sbase + OFF_BH + off);
                LDSM_X4(bl[gp * 2][0], bl[gp * 2][1],
                        bl[gp * 2 + 1][0], bl[gp * 2 + 1][1],
                        sbase + OFF_BL + off);
            }
#pragma unroll
            for (int mt = 0; mt < 2; mt++)
#pragma unroll
                for (int g = 0; g < 4; g++) {
                    MMA16816(acc[mt][g], ah[mt], bh[g]);
                    MMA16816(acc[mt][g], ah[mt], bl[g]);
                    MMA16816(acc[mt][g], al[mt], bh[g]);
                }
        }
    }

    // ---- Epilogue: z = acc + Wxb[char] -> gates -> c, h(hi/lo)
    const int gq = lane >> 2, t4 = lane & 3;
    const int jcol = j0 + jw * 8 + t4 * 2;     // absolute hidden j (even)

#pragma unroll
    for (int mt = 0; mt < 2; mt++) {
#pragma unroll
        for (int rr = 0; rr < 2; rr++) {
            const int b  = b0 + mw * 32 + mt * 16 + gq + rr * 8;
            const int ch = inputs[b * SEQ + t];
            const float* wrow = g_Wxb + (size_t)ch * 1024;
            float2 wx2[4];
#pragma unroll
            for (int g = 0; g < 4; g++)
                wx2[g] = *(const float2*)&wrow[g * 256 + jcol];
            float2 c2 = *(const float2*)&g_c[(size_t)b * HID + jcol];

            float cn[2], hn[2];
#pragma unroll
            for (int e = 0; e < 2; e++) {
                float zi = acc[mt][0][rr * 2 + e] + (e ? wx2[0].y : wx2[0].x);
                float zf = acc[mt][1][rr * 2 + e] + (e ? wx2[1].y : wx2[1].x);
                float zg = acc[mt][2][rr * 2 + e] + (e ? wx2[2].y : wx2[2].x);
                float zo = acc[mt][3][rr * 2 + e] + (e ? wx2[3].y : wx2[3].x);
                float ig = sigf(zi), fg = sigf(zf);
                float gg = tanh_(zg), og = sigf(zo);
                float cold = e ? c2.y : c2.x;
                float cc = fg * cold + ig * gg;
                cn[e] = cc;
                hn[e] = og * tanh_(cc);
            }
            *(float2*)&g_c[(size_t)b * HID + jcol] = make_float2(cn[0], cn[1]);

            __half h0 = __float2half(hn[0]), h1 = __float2half(hn[1]);
            __half l0 = __float2half(hn[0] - __half2float(h0));
            __half l1 = __float2half(hn[1] - __half2float(h1));
            *(__half2*)&hh_out[(size_t)b * HID + jcol] = __halves2half2(h0, h1);
            *(__half2*)&hl_out[(size_t)b * HID + jcol] = __halves2half2(l0, l1);
        }
    }
}

// ===========================================================================
// Dense + softmax (h = hh + hl reconstructed in f32)
// ===========================================================================
#define DROWS 8

__global__ __launch_bounds__(128) void dense_softmax_kernel(
    const float* __restrict__ Wd,   // [256, 128]
    const float* __restrict__ bd,   // [128]
    float*       __restrict__ out)  // [BATCH, 128]
{
    const __half* __restrict__ hh = g_hh[SEQ & 1];  // SEQ=40 even -> buffer 0
    const __half* __restrict__ hl = g_hl[SEQ & 1];
    const int b0  = blockIdx.x * DROWS;
    const int tid = threadIdx.x;

    __shared__ float hs[DROWS][HID];
    __shared__ float ls[DROWS][VOCAB];

#pragma unroll
    for (int s = 0; s < DROWS * HID / 128; s++) {
        int e = tid + s * 128;
        size_t ge = (size_t)b0 * HID + e;
        hs[e >> 8][e & 255] = __half2float(hh[ge]) + __half2float(hl[ge]);
    }
    __syncthreads();

    float acc[DROWS];
    float bv = bd[tid];
#pragma unroll
    for (int r = 0; r < DROWS; r++) acc[r] = bv;

#pragma unroll 8
    for (int k = 0; k < HID; k++) {
        float w = Wd[k * VOCAB + tid];
#pragma unroll
        for (int r = 0; r < DROWS; r++) acc[r] += hs[r][k] * w;
    }

#pragma unroll
    for (int r = 0; r < DROWS; r++) ls[r][tid] = acc[r];
    __syncthreads();

    const int w = tid >> 5, lane = tid & 31;
#pragma unroll
    for (int rr = 0; rr < 2; rr++) {
        int r = w * 2 + rr;
        float v[4];
        float m = -1e30f;
#pragma unroll
        for (int q = 0; q < 4; q++) {
            v[q] = ls[r][lane + q * 32];
            m = fmaxf(m, v[q]);
        }
#pragma unroll
        for (int o = 16; o > 0; o >>= 1) m = fmaxf(m, __shfl_xor_sync(0xffffffffu, m, o));
        float s = 0.0f;
#pragma unroll
        for (int q = 0; q < 4; q++) {
            v[q] = __expf(v[q] - m);
            s += v[q];
        }
#pragma unroll
        for (int o = 16; o > 0; o >>= 1) s += __shfl_xor_sync(0xffffffffu, s, o);
        float inv = 1.0f / s;
#pragma unroll
        for (int q = 0; q < 4; q++)
            out[(b0 + r) * VOCAB + lane + q * 32] = v[q] * inv;
    }
}

// ===========================================================================
extern "C" void kernel_launch(void* const* d_in, const int* in_sizes, int n_in,
                              void* d_out, int out_size) {
    const int*   inputs = (const int*)d_in[0];
    const float* Wx     = (const float*)d_in[1];
    const float* Wh     = (const float*)d_in[2];
    const float* b      = (const float*)d_in[3];
    const float* Wd     = (const float*)d_in[4];
    const float* bd     = (const float*)d_in[5];
    float*       out    = (float*)d_out;

    cudaFuncSetAttribute(lstm_step_kernel,
                         cudaFuncAttributeMaxDynamicSharedMemorySize, SMEM_TOTAL);

    init_state_kernel<<<(BATCH * HID + 255) / 256, 256>>>();
    prep_wh_kernel<<<(256 * 1024) / 256, 256>>>(Wh);
    prep_wxb_kernel<<<(128 * 1024) / 256, 256>>>(Wx, b);

    dim3 grid(BATCH / 64, 8);  // 128 x 8 = 1024 CTAs
    for (int t = 0; t < SEQ; t++)
        lstm_step_kernel<<<grid, 256, SMEM_TOTAL>>>(t, inputs);

    dense_softmax_kernel<<<BATCH / DROWS, 128>>>(Wd, bd, out);
}

// round 6
// speedup vs baseline: 1.3800x; 1.3219x over previous
#include <cuda_runtime.h>
#include <cuda_fp16.h>
#include <cstdint>

#define BATCH 8192
#define SEQ   40
#define HID   256
#define VOCAB 128

// ===========================================================================
// Global scratch (no cudaMalloc allowed)
// ===========================================================================
// A fragments (h state), ping-pong. block = grp*32 + kc*4 + ks*2 + pl,
// grp = batch/16 (512 groups), kc = k/32, ks = (k/16)&1, pl = hi/lo plane.
// Each block: 32 lanes x uint4 (4 mma a-regs).
__device__ __align__(16) uint4 g_Afrag[2][16384][32];
// B fragments (Wh split hi/lo). block = (jt*4+jw)*64 + kc*8 + ks*4 + pl*2 + gp.
// Each block: 32 lanes x uint4 = b-frags for gates gp*2 (x,y) and gp*2+1 (z,w).
__device__ __align__(16) uint4 g_Bfrag[2048][32];
__device__ float g_c[BATCH * HID];       // cell state
__device__ float g_Wxb[128 * 1024];      // Wx + bias folded
__device__ float g_hfin[BATCH * HID];    // final h (t=SEQ) for dense kernel

#define MMA16816(d, a, b) \
    asm volatile("mma.sync.aligned.m16n8k16.row.col.f32.f16.f16.f32 " \
        "{%0,%1,%2,%3}, {%4,%5,%6,%7}, {%8,%9}, {%0,%1,%2,%3};" \
        : "+f"((d)[0]), "+f"((d)[1]), "+f"((d)[2]), "+f"((d)[3]) \
        : "r"((a)[0]), "r"((a)[1]), "r"((a)[2]), "r"((a)[3]), \
          "r"((b)[0]), "r"((b)[1]))

__device__ __forceinline__ float sigf(float x) {
    return 1.0f / (1.0f + __expf(-x));
}
__device__ __forceinline__ float tanh_(float x) {
    float ax = fabsf(x);
    float e  = __expf(-2.0f * ax);
    float r  = (1.0f - e) / (1.0f + e);
    return copysignf(r, x);
}

// ===========================================================================
// Prep kernels
// ===========================================================================
// Scatter Wh (fp16 hi/lo split) into B-fragment layout.
// mma b-frag (m16n8k16): lane l, reg r holds {B[k=(l&3)*2 + r*8][n=l>>2], k+1}.
__global__ void prep_wh_kernel(const float* __restrict__ Wh) {
    int e = blockIdx.x * blockDim.x + threadIdx.x;  // 0 .. 262143
    int k = e >> 10, col = e & 1023;
    float v = Wh[e];
    __half hi = __float2half(v);
    __half lo = __float2half(v - __half2float(hi));
    int gate = col >> 8, j = col & 255;
    int jt = j >> 5, jw = (j >> 3) & 3, nl = j & 7;
    int kc = k >> 5, ks = (k >> 4) & 1, kk = k & 15;
    int gp = gate >> 1, gs = gate & 1;
    int lane = nl * 4 + ((kk & 7) >> 1);
    int reg  = kk >> 3;
    int hp   = kk & 1;
    int block = (jt * 4 + jw) * 64 + kc * 8 + ks * 4 + 0 * 2 + gp;  // pl folded below
    // pl=0 (hi) and pl=1 (lo) blocks differ by +2
    __half* base = (__half*)g_Bfrag;
    size_t idx0 = ((size_t)block * 32 + lane) * 8 + gs * 4 + reg * 2 + hp;
    size_t idx1 = ((size_t)(block + 2) * 32 + lane) * 8 + gs * 4 + reg * 2 + hp;
    base[idx0] = hi;
    base[idx1] = lo;
}

__global__ void prep_wxb_kernel(const float* __restrict__ Wx,
                                const float* __restrict__ bias) {
    int e = blockIdx.x * blockDim.x + threadIdx.x;  // 0 .. 131071
    g_Wxb[e] = Wx[e] + bias[e & 1023];
}

// Zero A-frag buffer 0 (h0 = 0, any layout) and c.
__global__ void init_state_kernel() {
    int i = blockIdx.x * blockDim.x + threadIdx.x;   // 0 .. 524287
    ((uint4*)g_Afrag[0])[i] = make_uint4(0, 0, 0, 0);
    ((float4*)g_c)[i] = make_float4(0.f, 0.f, 0.f, 0.f);
}

// ===========================================================================
// LSTM step: zero SMEM, zero barriers. CTA 256 thr = 8 warps (2 mw x 4 jw);
// warp tile M=32 x (4 gates x 8 j). All operands LDG'd in fragment layout.
// ===========================================================================
__global__ __launch_bounds__(256, 2) void lstm_step_kernel(
    int t,
    const int* __restrict__ inputs)     // [BATCH, SEQ]
{
    const int tid  = threadIdx.x;
    const int lane = tid & 31, wid = tid >> 5;
    const int mw = wid >> 2;          // 0..1
    const int jw = wid & 3;           // 0..3
    const int b0 = blockIdx.x * 64;
    const int jt = blockIdx.y;        // 0..7

    const uint4* __restrict__ A = &g_Afrag[t & 1][0][lane];      // stride 32
    const uint4* __restrict__ B = &g_Bfrag[0][lane];             // stride 32
    uint32_t* __restrict__ Aout = (uint32_t*)g_Afrag[(t + 1) & 1];

    const int agrp0 = (b0 >> 4) + mw * 2;          // group of mt=0
    const int bbase = (jt * 4 + jw) * 64;

    float acc[2][4][4];
#pragma unroll
    for (int mt = 0; mt < 2; mt++)
#pragma unroll
        for (int g = 0; g < 4; g++)
#pragma unroll
            for (int e = 0; e < 4; e++) acc[mt][g][e] = 0.0f;

#pragma unroll 1
    for (int kc = 0; kc < 8; kc++) {
#pragma unroll
        for (int ks = 0; ks < 2; ks++) {
            uint4 av[2][2], bv[2][2];   // [pl][mt], [pl][gp]
#pragma unroll
            for (int pl = 0; pl < 2; pl++) {
#pragma unroll
                for (int mt = 0; mt < 2; mt++)
                    av[pl][mt] = A[(size_t)((agrp0 + mt) * 32 + kc * 4 + ks * 2 + pl) * 32];
#pragma unroll
                for (int gp = 0; gp < 2; gp++)
                    bv[pl][gp] = B[(size_t)(bbase + kc * 8 + ks * 4 + pl * 2 + gp) * 32];
            }
            uint32_t ah[2][4] = {{av[0][0].x, av[0][0].y, av[0][0].z, av[0][0].w},
                                 {av[0][1].x, av[0][1].y, av[0][1].z, av[0][1].w}};
            uint32_t al[2][4] = {{av[1][0].x, av[1][0].y, av[1][0].z, av[1][0].w},
                                 {av[1][1].x, av[1][1].y, av[1][1].z, av[1][1].w}};
            uint32_t bh[4][2] = {{bv[0][0].x, bv[0][0].y}, {bv[0][0].z, bv[0][0].w},
                                 {bv[0][1].x, bv[0][1].y}, {bv[0][1].z, bv[0][1].w}};
            uint32_t bl[4][2] = {{bv[1][0].x, bv[1][0].y}, {bv[1][0].z, bv[1][0].w},
                                 {bv[1][1].x, bv[1][1].y}, {bv[1][1].z, bv[1][1].w}};
#pragma unroll
            for (int mt = 0; mt < 2; mt++)
#pragma unroll
                for (int g = 0; g < 4; g++) {
                    MMA16816(acc[mt][g], ah[mt], bh[g]);
                    MMA16816(acc[mt][g], ah[mt], bl[g]);
                    MMA16816(acc[mt][g], al[mt], bh[g]);
                }
        }
    }

    // ---- Epilogue: z = acc + Wxb[char] -> gates -> c; h stored as A-frags.
    const int gq = lane >> 2, t4 = lane & 3;
    const int jcol = jt * 32 + jw * 8 + t4 * 2;   // even
    // A-frag store geometry: kc=jt, ks=jw>>1, lane_store == lane,
    // reg = rr + 2*(jw&1).
    const int blk_base = jt * 4 + (jw >> 1) * 2;  // + grp*32 + pl

#pragma unroll
    for (int mt = 0; mt < 2; mt++) {
        const int grp = agrp0 + mt;
#pragma unroll
        for (int rr = 0; rr < 2; rr++) {
            const int b  = b0 + mw * 32 + mt * 16 + gq + rr * 8;
            const int ch = inputs[b * SEQ + t];
            const float* wrow = g_Wxb + (size_t)ch * 1024;
            float2 wx2[4];
#pragma unroll
            for (int g = 0; g < 4; g++)
                wx2[g] = *(const float2*)&wrow[g * 256 + jcol];
            float2 c2 = *(const float2*)&g_c[(size_t)b * HID + jcol];

            float cn[2], hn[2];
#pragma unroll
            for (int e = 0; e < 2; e++) {
                float zi = acc[mt][0][rr * 2 + e] + (e ? wx2[0].y : wx2[0].x);
                float zf = acc[mt][1][rr * 2 + e] + (e ? wx2[1].y : wx2[1].x);
                float zg = acc[mt][2][rr * 2 + e] + (e ? wx2[2].y : wx2[2].x);
                float zo = acc[mt][3][rr * 2 + e] + (e ? wx2[3].y : wx2[3].x);
                float ig = sigf(zi), fg = sigf(zf);
                float gg = tanh_(zg), og = sigf(zo);
                float cold = e ? c2.y : c2.x;
                float cc = fg * cold + ig * gg;
                cn[e] = cc;
                hn[e] = og * tanh_(cc);
            }
            *(float2*)&g_c[(size_t)b * HID + jcol] = make_float2(cn[0], cn[1]);

            // split h -> fp16 hi/lo, store into next step's A-frag layout
            __half h0 = __float2half(hn[0]), h1 = __float2half(hn[1]);
            __half l0 = __float2half(hn[0] - __half2float(h0));
            __half l1 = __float2half(hn[1] - __half2float(h1));
            __half2 phi = __halves2half2(h0, h1);
            __half2 plo = __halves2half2(l0, l1);
            const int reg = rr + 2 * (jw & 1);
            uint32_t idx_hi = (uint32_t)(((grp * 32 + blk_base + 0) * 32 + lane) * 4 + reg);
            uint32_t idx_lo = (uint32_t)(((grp * 32 + blk_base + 1) * 32 + lane) * 4 + reg);
            Aout[idx_hi] = *(uint32_t*)&phi;
            Aout[idx_lo] = *(uint32_t*)&plo;

            if (t == SEQ - 1)
                *(float2*)&g_hfin[(size_t)b * HID + jcol] = make_float2(hn[0], hn[1]);
        }
    }
}

// ===========================================================================
// Dense + softmax (reads g_hfin, float)
// ===========================================================================
#define DROWS 8

__global__ __launch_bounds__(128) void dense_softmax_kernel(
    const float* __restrict__ Wd,   // [256, 128]
    const float* __restrict__ bd,   // [128]
    float*       __restrict__ out)  // [BATCH, 128]
{
    const int b0  = blockIdx.x * DROWS;
    const int tid = threadIdx.x;

    __shared__ float hs[DROWS][HID];
    __shared__ float ls[DROWS][VOCAB];

#pragma unroll
    for (int s = 0; s < DROWS * HID / 128; s++) {
        int e = tid + s * 128;
        hs[e >> 8][e & 255] = g_hfin[(size_t)b0 * HID + e];
    }
    __syncthreads();

    float acc[DROWS];
    float bv = bd[tid];
#pragma unroll
    for (int r = 0; r < DROWS; r++) acc[r] = bv;

#pragma unroll 8
    for (int k = 0; k < HID; k++) {
        float w = Wd[k * VOCAB + tid];
#pragma unroll
        for (int r = 0; r < DROWS; r++) acc[r] += hs[r][k] * w;
    }

#pragma unroll
    for (int r = 0; r < DROWS; r++) ls[r][tid] = acc[r];
    __syncthreads();

    const int w = tid >> 5, lane = tid & 31;
#pragma unroll
    for (int rr = 0; rr < 2; rr++) {
        int r = w * 2 + rr;
        float v[4];
        float m = -1e30f;
#pragma unroll
        for (int q = 0; q < 4; q++) {
            v[q] = ls[r][lane + q * 32];
            m = fmaxf(m, v[q]);
        }
#pragma unroll
        for (int o = 16; o > 0; o >>= 1) m = fmaxf(m, __shfl_xor_sync(0xffffffffu, m, o));
        float s = 0.0f;
#pragma unroll
        for (int q = 0; q < 4; q++) {
            v[q] = __expf(v[q] - m);
            s += v[q];
        }
#pragma unroll
        for (int o = 16; o > 0; o >>= 1) s += __shfl_xor_sync(0xffffffffu, s, o);
        float inv = 1.0f / s;
#pragma unroll
        for (int q = 0; q < 4; q++)
            out[(b0 + r) * VOCAB + lane + q * 32] = v[q] * inv;
    }
}

// ===========================================================================
extern "C" void kernel_launch(void* const* d_in, const int* in_sizes, int n_in,
                              void* d_out, int out_size) {
    const int*   inputs = (const int*)d_in[0];
    const float* Wx     = (const float*)d_in[1];
    const float* Wh     = (const float*)d_in[2];
    const float* b      = (const float*)d_in[3];
    const float* Wd     = (const float*)d_in[4];
    const float* bd     = (const float*)d_in[5];
    float*       out    = (float*)d_out;

    init_state_kernel<<<2048, 256>>>();
    prep_wh_kernel<<<1024, 256>>>(Wh);
    prep_wxb_kernel<<<512, 256>>>(Wx, b);

    dim3 grid(BATCH / 64, 8);  // 128 x 8 = 1024 CTAs
    for (int t = 0; t < SEQ; t++)
        lstm_step_kernel<<<grid, 256>>>(t, inputs);

    dense_softmax_kernel<<<BATCH / DROWS, 128>>>(Wd, bd, out);
}

// round 7
// speedup vs baseline: 1.4369x; 1.0413x over previous
#include <cuda_runtime.h>
#include <cuda_fp16.h>
#include <cstdint>

#define BATCH 8192
#define SEQ   40
#define HID   256
#define VOCAB 128

// ===========================================================================
// Global scratch (no cudaMalloc allowed)
// ===========================================================================
// A fragments (h state), ping-pong. block = grp*32 + kc*4 + ks*2 + pl,
// grp = batch/16, kc = k/32, ks = (k/16)&1, pl = hi/lo. 32 lanes x uint4.
__device__ __align__(16) uint4 g_Afrag[2][16384][32];
// B fragments (Wh split hi/lo). block = (jt*4+jw)*64 + (kc*2+ks)*4 + pl*2 + gp.
__device__ __align__(16) uint4 g_Bfrag[2048][32];
__device__ float g_c[BATCH * HID];       // cell state
__device__ float g_Wxb[128 * 1024];      // Wx + bias folded
__device__ float g_hfin[BATCH * HID];    // final h for dense kernel
__device__ int   g_inT[SEQ * BATCH];     // transposed chars [t][b]

__device__ __forceinline__ uint32_t smem_to_u32(const void* p) {
    uint32_t a;
    asm("{ .reg .u64 tmp; cvta.to.shared.u64 tmp, %1; cvt.u32.u64 %0, tmp; }"
        : "=r"(a) : "l"(p));
    return a;
}

#define CP_ASYNC16(dst, src) \
    asm volatile("cp.async.cg.shared.global [%0], [%1], 16;" \
        :: "r"(dst), "l"(src) : "memory")
#define CP_COMMIT() asm volatile("cp.async.commit_group;" ::: "memory")
#define CP_WAIT0()  asm volatile("cp.async.wait_group 0;" ::: "memory")

#define LDS128(r0, r1, r2, r3, addr) \
    asm volatile("ld.shared.v4.b32 {%0,%1,%2,%3}, [%4];" \
        : "=r"(r0), "=r"(r1), "=r"(r2), "=r"(r3) : "r"(addr))

#define MMA16816(d, a, b0, b1) \
    asm volatile("mma.sync.aligned.m16n8k16.row.col.f32.f16.f16.f32 " \
        "{%0,%1,%2,%3}, {%4,%5,%6,%7}, {%8,%9}, {%0,%1,%2,%3};" \
        : "+f"((d)[0]), "+f"((d)[1]), "+f"((d)[2]), "+f"((d)[3]) \
        : "r"((a)[0]), "r"((a)[1]), "r"((a)[2]), "r"((a)[3]), \
          "r"(b0), "r"(b1))

__device__ __forceinline__ float sigf(float x) {
    return 1.0f / (1.0f + __expf(-x));
}
__device__ __forceinline__ float tanh_(float x) {
    float ax = fabsf(x);
    float e  = __expf(-2.0f * ax);
    float r  = (1.0f - e) / (1.0f + e);
    return copysignf(r, x);
}

// ===========================================================================
// Prep kernels
// ===========================================================================
__global__ void prep_wh_kernel(const float* __restrict__ Wh) {
    int e = blockIdx.x * blockDim.x + threadIdx.x;  // 0 .. 262143
    int k = e >> 10, col = e & 1023;
    float v = Wh[e];
    __half hi = __float2half(v);
    __half lo = __float2half(v - __half2float(hi));
    int gate = col >> 8, j = col & 255;
    int jt = j >> 5, jw = (j >> 3) & 3, nl = j & 7;
    int kc = k >> 5, ks = (k >> 4) & 1, kk = k & 15;
    int gp = gate >> 1, gs = gate & 1;
    int lane = nl * 4 + ((kk & 7) >> 1);
    int reg  = kk >> 3;
    int hp   = kk & 1;
    int block = (jt * 4 + jw) * 64 + kc * 8 + ks * 4 + gp;
    __half* base = (__half*)g_Bfrag;
    size_t idx0 = ((size_t)block * 32 + lane) * 8 + gs * 4 + reg * 2 + hp;
    size_t idx1 = ((size_t)(block + 2) * 32 + lane) * 8 + gs * 4 + reg * 2 + hp;
    base[idx0] = hi;
    base[idx1] = lo;
}

__global__ void prep_wxb_kernel(const float* __restrict__ Wx,
                                const float* __restrict__ bias) {
    int e = blockIdx.x * blockDim.x + threadIdx.x;  // 0 .. 131071
    g_Wxb[e] = Wx[e] + bias[e & 1023];
}

__global__ void prep_in_kernel(const int* __restrict__ inputs) {
    int i = blockIdx.x * blockDim.x + threadIdx.x;  // 0 .. 327679
    int b = i / SEQ, tt = i - b * SEQ;
    g_inT[tt * BATCH + b] = inputs[i];
}

__global__ void init_state_kernel() {
    int i = blockIdx.x * blockDim.x + threadIdx.x;   // 0 .. 524287
    ((uint4*)g_Afrag[0])[i] = make_uint4(0, 0, 0, 0);
    ((float4*)g_c)[i] = make_float4(0.f, 0.f, 0.f, 0.f);
}

// ===========================================================================
// LSTM step. CTA 256 thr = 8 warps (2 mw x 4 jw); warp tile M=32 x (4g x 8j).
// A tile (64 batch x K=256 x hi/lo = 64KB) staged in SMEM once via cp.async;
// B fragments LDG'd with manual double-buffer prefetch. One barrier total.
// ===========================================================================
#define SMEM_TOTAL 65536

__global__ __launch_bounds__(256, 2) void lstm_step_kernel(int t) {
    extern __shared__ __align__(16) unsigned char smem[];
    const uint32_t sA = smem_to_u32(smem);
    const int tid  = threadIdx.x;
    const int lane = tid & 31, wid = tid >> 5;
    const int mw = wid >> 2;          // 0..1
    const int jw = wid & 3;           // 0..3
    const int bx = blockIdx.x;        // 0..127
    const int jt = blockIdx.y;        // 0..7

    // ---- stage A tile (128 blocks = this CTA's 4 batch-groups) into SMEM
    {
        const uint4* Asrc = &g_Afrag[t & 1][bx * 128][0];
#pragma unroll
        for (int i = 0; i < 16; i++)
            CP_ASYNC16(sA + tid * 16 + i * 4096,
                       (const char*)(Asrc + i * 256 + tid));
        CP_COMMIT();
    }

    // ---- prefetch chars (epilogue) while A streams
    const int gq = lane >> 2, t4 = lane & 3;
    int ch[2][2];
#pragma unroll
    for (int mt = 0; mt < 2; mt++)
#pragma unroll
        for (int rr = 0; rr < 2; rr++)
            ch[mt][rr] = g_inT[t * BATCH + bx * 64 + mw * 32 + mt * 16 + gq + rr * 8];

    // ---- prefetch B iter 0
    const uint4* __restrict__ Bp = &g_Bfrag[(jt * 4 + jw) * 64][lane];
    uint4 bv0 = Bp[0], bv1 = Bp[32], bv2 = Bp[64], bv3 = Bp[96];

    CP_WAIT0();
    __syncthreads();

    float acc[2][4][4];
#pragma unroll
    for (int mt = 0; mt < 2; mt++)
#pragma unroll
        for (int g = 0; g < 4; g++)
#pragma unroll
            for (int e = 0; e < 4; e++) acc[mt][g][e] = 0.0f;

    const uint32_t aoff0 = sA + ((mw * 2 + 0) * 32) * 512 + lane * 16;
    const uint32_t aoff1 = sA + ((mw * 2 + 1) * 32) * 512 + lane * 16;

#pragma unroll 2
    for (int it = 0; it < 16; it++) {
        // prefetch next iter's B (4 consecutive blocks = 128 uint4 stride)
        uint4 bn0, bn1, bn2, bn3;
        if (it < 15) {
            const uint4* p = Bp + (it + 1) * 128;
            bn0 = p[0]; bn1 = p[32]; bn2 = p[64]; bn3 = p[96];
        } else {
            bn0 = bv0; bn1 = bv1; bn2 = bv2; bn3 = bv3;
        }

        // A via LDS (conflict-free)
        uint32_t ah[2][4], al[2][4];
        {
            uint32_t o = it * 1024;   // (it*2 blocks) * 512B
            LDS128(ah[0][0], ah[0][1], ah[0][2], ah[0][3], aoff0 + o);
            LDS128(al[0][0], al[0][1], al[0][2], al[0][3], aoff0 + o + 512);
            LDS128(ah[1][0], ah[1][1], ah[1][2], ah[1][3], aoff1 + o);
            LDS128(al[1][0], al[1][1], al[1][2], al[1][3], aoff1 + o + 512);
        }

#pragma unroll
        for (int mt = 0; mt < 2; mt++) {
            MMA16816(acc[mt][0], ah[mt], bv0.x, bv0.y);
            MMA16816(acc[mt][1], ah[mt], bv0.z, bv0.w);
            MMA16816(acc[mt][2], ah[mt], bv1.x, bv1.y);
            MMA16816(acc[mt][3], ah[mt], bv1.z, bv1.w);
            MMA16816(acc[mt][0], ah[mt], bv2.x, bv2.y);
            MMA16816(acc[mt][1], ah[mt], bv2.z, bv2.w);
            MMA16816(acc[mt][2], ah[mt], bv3.x, bv3.y);
            MMA16816(acc[mt][3], ah[mt], bv3.z, bv3.w);
            MMA16816(acc[mt][0], al[mt], bv0.x, bv0.y);
            MMA16816(acc[mt][1], al[mt], bv0.z, bv0.w);
            MMA16816(acc[mt][2], al[mt], bv1.x, bv1.y);
            MMA16816(acc[mt][3], al[mt], bv1.z, bv1.w);
        }
        bv0 = bn0; bv1 = bn1; bv2 = bn2; bv3 = bn3;
    }

    // ---- Epilogue: z = acc + Wxb[char] -> gates -> c; h stored as A-frags.
    const int jcol = jt * 32 + jw * 8 + t4 * 2;   // even
    const int blk_base = jt * 4 + (jw >> 1) * 2;  // + grp*32 + pl
    uint32_t* __restrict__ Aout = (uint32_t*)g_Afrag[(t + 1) & 1];

#pragma unroll
    for (int mt = 0; mt < 2; mt++) {
        const int grp = bx * 4 + mw * 2 + mt;
#pragma unroll
        for (int rr = 0; rr < 2; rr++) {
            const int b = bx * 64 + mw * 32 + mt * 16 + gq + rr * 8;
            const float* wrow = g_Wxb + (size_t)ch[mt][rr] * 1024;
            float2 wx2[4];
#pragma unroll
            for (int g = 0; g < 4; g++)
                wx2[g] = *(const float2*)&wrow[g * 256 + jcol];
            float2 c2 = *(const float2*)&g_c[(size_t)b * HID + jcol];

            float cn[2], hn[2];
#pragma unroll
            for (int e = 0; e < 2; e++) {
                float zi = acc[mt][0][rr * 2 + e] + (e ? wx2[0].y : wx2[0].x);
                float zf = acc[mt][1][rr * 2 + e] + (e ? wx2[1].y : wx2[1].x);
                float zg = acc[mt][2][rr * 2 + e] + (e ? wx2[2].y : wx2[2].x);
                float zo = acc[mt][3][rr * 2 + e] + (e ? wx2[3].y : wx2[3].x);
                float ig = sigf(zi), fg = sigf(zf);
                float gg = tanh_(zg), og = sigf(zo);
                float cold = e ? c2.y : c2.x;
                float cc = fg * cold + ig * gg;
                cn[e] = cc;
                hn[e] = og * tanh_(cc);
            }
            *(float2*)&g_c[(size_t)b * HID + jcol] = make_float2(cn[0], cn[1]);

            __half h0 = __float2half(hn[0]), h1 = __float2half(hn[1]);
            __half l0 = __float2half(hn[0] - __half2float(h0));
            __half l1 = __float2half(hn[1] - __half2float(h1));
            __half2 phi = __halves2half2(h0, h1);
            __half2 plo = __halves2half2(l0, l1);
            const int reg = rr + 2 * (jw & 1);
            uint32_t idx_hi = (uint32_t)(((grp * 32 + blk_base + 0) * 32 + lane) * 4 + reg);
            uint32_t idx_lo = (uint32_t)(((grp * 32 + blk_base + 1) * 32 + lane) * 4 + reg);
            Aout[idx_hi] = *(uint32_t*)&phi;
            Aout[idx_lo] = *(uint32_t*)&plo;

            if (t == SEQ - 1)
                *(float2*)&g_hfin[(size_t)b * HID + jcol] = make_float2(hn[0], hn[1]);
        }
    }
}

// ===========================================================================
// Dense + softmax (reads g_hfin, float)
// ===========================================================================
#define DROWS 8

__global__ __launch_bounds__(128) void dense_softmax_kernel(
    const float* __restrict__ Wd,   // [256, 128]
    const float* __restrict__ bd,   // [128]
    float*       __restrict__ out)  // [BATCH, 128]
{
    const int b0  = blockIdx.x * DROWS;
    const int tid = threadIdx.x;

    __shared__ float hs[DROWS][HID];
    __shared__ float ls[DROWS][VOCAB];

#pragma unroll
    for (int s = 0; s < DROWS * HID / 128; s++) {
        int e = tid + s * 128;
        hs[e >> 8][e & 255] = g_hfin[(size_t)b0 * HID + e];
    }
    __syncthreads();

    float acc[DROWS];
    float bv = bd[tid];
#pragma unroll
    for (int r = 0; r < DROWS; r++) acc[r] = bv;

#pragma unroll 8
    for (int k = 0; k < HID; k++) {
        float w = Wd[k * VOCAB + tid];
#pragma unroll
        for (int r = 0; r < DROWS; r++) acc[r] += hs[r][k] * w;
    }

#pragma unroll
    for (int r = 0; r < DROWS; r++) ls[r][tid] = acc[r];
    __syncthreads();

    const int w = tid >> 5, lane = tid & 31;
#pragma unroll
    for (int rr = 0; rr < 2; rr++) {
        int r = w * 2 + rr;
        float v[4];
        float m = -1e30f;
#pragma unroll
        for (int q = 0; q < 4; q++) {
            v[q] = ls[r][lane + q * 32];
            m = fmaxf(m, v[q]);
        }
#pragma unroll
        for (int o = 16; o > 0; o >>= 1) m = fmaxf(m, __shfl_xor_sync(0xffffffffu, m, o));
        float s = 0.0f;
#pragma unroll
        for (int q = 0; q < 4; q++) {
            v[q] = __expf(v[q] - m);
            s += v[q];
        }
#pragma unroll
        for (int o = 16; o > 0; o >>= 1) s += __shfl_xor_sync(0xffffffffu, s, o);
        float inv = 1.0f / s;
#pragma unroll
        for (int q = 0; q < 4; q++)
            out[(b0 + r) * VOCAB + lane + q * 32] = v[q] * inv;
    }
}

// ===========================================================================
extern "C" void kernel_launch(void* const* d_in, const int* in_sizes, int n_in,
                              void* d_out, int out_size) {
    const int*   inputs = (const int*)d_in[0];
    const float* Wx     = (const float*)d_in[1];
    const float* Wh     = (const float*)d_in[2];
    const float* b      = (const float*)d_in[3];
    const float* Wd     = (const float*)d_in[4];
    const float* bd     = (const float*)d_in[5];
    float*       out    = (float*)d_out;

    cudaFuncSetAttribute(lstm_step_kernel,
                         cudaFuncAttributeMaxDynamicSharedMemorySize, SMEM_TOTAL);

    init_state_kernel<<<2048, 256>>>();
    prep_wh_kernel<<<1024, 256>>>(Wh);
    prep_wxb_kernel<<<512, 256>>>(Wx, b);
    prep_in_kernel<<<(BATCH * SEQ + 255) / 256, 256>>>(inputs);

    dim3 grid(BATCH / 64, 8);  // 128 x 8 = 1024 CTAs
    for (int t = 0; t < SEQ; t++)
        lstm_step_kernel<<<grid, 256, SMEM_TOTAL>>>(t);

    dense_softmax_kernel<<<BATCH / DROWS, 128>>>(Wd, bd, out);
}